// round 1
// baseline (speedup 1.0000x reference)
#include <cuda_runtime.h>

// Row-wise L1 normalization: y[b,r,:] = x[b,r,:] / max(sum(x[b,r,:]), 1e-5)
// Shapes: [16, 2048, 2048] fp32. One CTA per row; 256 threads x 8 floats.
// Fused single-pass: row lives in registers between reduce and scale.

#define ROW_LEN 2048
#define THREADS 256
#define V4_PER_ROW (ROW_LEN / 4)          // 512 float4 per row
#define V4_PER_THREAD (V4_PER_ROW / THREADS) // 2

__global__ __launch_bounds__(THREADS)
void rownorm_kernel(const float4* __restrict__ in, float4* __restrict__ out) {
    const long long base = (long long)blockIdx.x * V4_PER_ROW;
    const int t = threadIdx.x;

    // Load 8 floats (2 float4) per thread, front-batched for MLP.
    float4 a = in[base + t];
    float4 b = in[base + THREADS + t];

    float s = (a.x + a.y) + (a.z + a.w) + (b.x + b.y) + (b.z + b.w);

    // Warp reduce
    #pragma unroll
    for (int o = 16; o > 0; o >>= 1)
        s += __shfl_xor_sync(0xffffffffu, s, o);

    __shared__ float ws[THREADS / 32];
    if ((t & 31) == 0) ws[t >> 5] = s;
    __syncthreads();

    if (t < 32) {
        float v = (t < THREADS / 32) ? ws[t] : 0.0f;
        #pragma unroll
        for (int o = (THREADS / 32) / 2; o > 0; o >>= 1)
            v += __shfl_xor_sync(0xffffffffu, v, o);
        if (t == 0) ws[0] = v;
    }
    __syncthreads();

    const float inv = 1.0f / fmaxf(ws[0], 1e-5f);

    a.x *= inv; a.y *= inv; a.z *= inv; a.w *= inv;
    b.x *= inv; b.y *= inv; b.z *= inv; b.w *= inv;

    out[base + t] = a;
    out[base + THREADS + t] = b;
}

extern "C" void kernel_launch(void* const* d_in, const int* in_sizes, int n_in,
                              void* d_out, int out_size) {
    const float4* in = (const float4*)d_in[0];
    float4* out = (float4*)d_out;
    const int n_rows = in_sizes[0] / ROW_LEN;   // 16 * 2048 = 32768
    rownorm_kernel<<<n_rows, THREADS>>>(in, out);
}

// round 2
// speedup vs baseline: 1.0296x; 1.0296x over previous
#include <cuda_runtime.h>

// Row-wise L1 normalization: y[b,r,:] = x[b,r,:] / max(sum(x[b,r,:]), 1e-5)
// [16, 2048, 2048] fp32. One WARP per row: 32 lanes x 16 float4 = 2048 floats.
// No __syncthreads on the critical path; warp-shuffle reduction only.
// Deep per-warp MLP (16 front-batched LDG.128) to keep HBM saturated.

#define ROW_LEN 2048
#define V4_PER_ROW (ROW_LEN / 4)     // 512
#define V4_PER_LANE (V4_PER_ROW / 32) // 16
#define WARPS_PER_CTA 8
#define THREADS (WARPS_PER_CTA * 32)

__global__ __launch_bounds__(THREADS)
void rownorm_warp_kernel(const float4* __restrict__ in, float4* __restrict__ out) {
    const int warp = blockIdx.x * WARPS_PER_CTA + (threadIdx.x >> 5);
    const int lane = threadIdx.x & 31;
    const long long base = (long long)warp * V4_PER_ROW + lane;

    // Front-batched loads: 16 independent LDG.128 per lane (MLP=16).
    float4 v[V4_PER_LANE];
    #pragma unroll
    for (int i = 0; i < V4_PER_LANE; i++)
        v[i] = __ldcs(&in[base + i * 32]);

    // Per-lane partial sum (pairwise-ish tree for a bit of accuracy + ILP).
    float s = 0.0f;
    #pragma unroll
    for (int i = 0; i < V4_PER_LANE; i++)
        s += (v[i].x + v[i].y) + (v[i].z + v[i].w);

    // Warp reduction — no barriers.
    #pragma unroll
    for (int o = 16; o > 0; o >>= 1)
        s += __shfl_xor_sync(0xffffffffu, s, o);

    const float inv = 1.0f / fmaxf(s, 1e-5f);

    #pragma unroll
    for (int i = 0; i < V4_PER_LANE; i++) {
        float4 w = v[i];
        w.x *= inv; w.y *= inv; w.z *= inv; w.w *= inv;
        __stcs(&out[base + i * 32], w);
    }
}

extern "C" void kernel_launch(void* const* d_in, const int* in_sizes, int n_in,
                              void* d_out, int out_size) {
    const float4* in = (const float4*)d_in[0];
    float4* out = (float4*)d_out;
    const int n_rows = in_sizes[0] / ROW_LEN;          // 32768
    const int n_ctas = n_rows / WARPS_PER_CTA;         // 4096
    rownorm_warp_kernel<<<n_ctas, THREADS>>>(in, out);
}